// round 1
// baseline (speedup 1.0000x reference)
#include <cuda_runtime.h>
#include <math.h>
#include <stdint.h>

// Problem constants
#define B_SZ   8
#define S_LEN  2048
#define HID    256
#define EMBD   256
#define VOC    100
#define BS     (B_SZ * S_LEN)       // 16384
#define G3     768                  // 3*HID

// ---------------------------------------------------------------------------
// Scratch (static device globals; no cudaMalloc allowed)
// ---------------------------------------------------------------------------
__device__ float g_xg[BS * G3];      // xg = emb @ w_ih^T + b_ih   (48 MB)
__device__ float g_h[BS * HID];      // all_h                      (16 MB)
__device__ float g_keys[BS * HID];   // keys                       (16 MB)
__device__ float g_ctx[BS * HID];    // attention context          (16 MB)
__device__ float g_comb[BS * HID];   // combined (tanh)            (16 MB)

__device__ __forceinline__ float sigmoidf_(float x) {
    return 1.0f / (1.0f + __expf(-x));
}

// ---------------------------------------------------------------------------
// Generic SGEMM:  C[M,N] = A[M,K] @ W[N,K]^T + bias, optional tanh.
//  - idx != null : A-row gather (embedding lookup), A has K1 cols.
//  - A2 != null  : concatenated K dim, k >= K1 reads A2 (K-K1 cols).
// 128x128 tile, BK=8, 256 threads, 8x8 per-thread microkernel.
// ---------------------------------------------------------------------------
__global__ void __launch_bounds__(256, 2)
gemm_kernel(const float* __restrict__ A, const float* __restrict__ A2, int K1,
            const int* __restrict__ idx,
            const float* __restrict__ W, const float* __restrict__ bias,
            float* __restrict__ C, int M, int N, int K, int act)
{
    __shared__ float As[8][128];
    __shared__ float Ws[8][128];

    const int bm  = blockIdx.y * 128;
    const int bn  = blockIdx.x * 128;
    const int tid = threadIdx.x;
    const int tx  = tid & 15;
    const int ty  = tid >> 4;
    const int lr  = tid >> 1;         // 0..127
    const int lk  = (tid & 1) << 2;   // 0 or 4

    float acc[8][8];
#pragma unroll
    for (int i = 0; i < 8; i++)
#pragma unroll
        for (int j = 0; j < 8; j++) acc[i][j] = 0.0f;

    int arow = bm + lr;                 // M is a multiple of 128 here
    if (idx) arow = idx[arow];
    const int wn = bn + lr;
    const int K2 = K - K1;

    for (int k0 = 0; k0 < K; k0 += 8) {
        const int kk = k0 + lk;
        float4 av;
        if (kk < K1) av = *(const float4*)(A  + (size_t)arow * K1 + kk);
        else         av = *(const float4*)(A2 + (size_t)arow * K2 + (kk - K1));
        As[lk + 0][lr] = av.x; As[lk + 1][lr] = av.y;
        As[lk + 2][lr] = av.z; As[lk + 3][lr] = av.w;

        float4 wv = make_float4(0.f, 0.f, 0.f, 0.f);
        if (wn < N) wv = *(const float4*)(W + (size_t)wn * K + kk);
        Ws[lk + 0][lr] = wv.x; Ws[lk + 1][lr] = wv.y;
        Ws[lk + 2][lr] = wv.z; Ws[lk + 3][lr] = wv.w;

        __syncthreads();
#pragma unroll
        for (int q = 0; q < 8; q++) {
            float a[8], b[8];
            *(float4*)&a[0] = *(const float4*)&As[q][ty * 4];
            *(float4*)&a[4] = *(const float4*)&As[q][64 + ty * 4];
            *(float4*)&b[0] = *(const float4*)&Ws[q][tx * 4];
            *(float4*)&b[4] = *(const float4*)&Ws[q][64 + tx * 4];
#pragma unroll
            for (int i = 0; i < 8; i++)
#pragma unroll
                for (int j = 0; j < 8; j++)
                    acc[i][j] = fmaf(a[i], b[j], acc[i][j]);
        }
        __syncthreads();
    }

#pragma unroll
    for (int i = 0; i < 8; i++) {
        const int r = bm + ((i < 4) ? (ty * 4 + i) : (64 + ty * 4 + i - 4));
#pragma unroll
        for (int j = 0; j < 8; j++) {
            const int c = bn + ((j < 4) ? (tx * 4 + j) : (64 + tx * 4 + j - 4));
            if (c < N) {
                float v = acc[i][j] + bias[c];
                if (act) v = tanhf(v);
                C[(size_t)r * N + c] = v;
            }
        }
    }
}

// ---------------------------------------------------------------------------
// GRU scan. Grid = 64 CTAs = 8 batches x (cluster of 8 CTAs). 384 thr/CTA.
// Each CTA owns 32 hidden indices j = rank*32..+31 (all 3 gates), keeps its
// 96x256 w_hh slice in registers. h replicated in each CTA's smem, sliced
// into 4 K-parts (part p = h[p*64..p*64+63]) for conflict-free float4 reads.
// Thread t: dot d = t>>2 (d = gate*32 + jj), K-part p = t&3 (64 FMAs),
// shfl-reduce over the 4-lane group. Double-buffered h + one cluster.sync
// per step; owners broadcast h_new to all 8 CTAs via st.shared::cluster.
// ---------------------------------------------------------------------------
__global__ void __cluster_dims__(8, 1, 1) __launch_bounds__(384, 1)
gru_kernel(const float* __restrict__ xg, const float* __restrict__ w_hh,
           const float* __restrict__ b_hh, float* __restrict__ all_h,
           float* __restrict__ hid_out)
{
    __shared__ float h_sm[2][4][68];   // [buf][k-part][64 (+4 pad)]
    __shared__ float dots_sm[96];
    __shared__ float xg_sm[96];

    unsigned rank;
    asm("mov.u32 %0, %%cluster_ctarank;" : "=r"(rank));
    const int b  = blockIdx.x >> 3;
    const int t  = threadIdx.x;
    const int d  = t >> 2;            // 0..95
    const int p  = t & 3;             // 0..3
    const int g  = d >> 5;            // gate 0..2  (r,z,n)
    const int jj = d & 31;
    const int grow = (g << 8) + ((int)rank << 5) + jj;  // row in [0,768)

    // w_hh slice -> registers (64 floats / thread)
    float4 w[16];
    {
        const float4* wr = (const float4*)(w_hh + (size_t)grow * 256 + (p << 6));
#pragma unroll
        for (int i = 0; i < 16; i++) w[i] = wr[i];
    }
    float bhr = 0.f, bhz = 0.f, bhn = 0.f;
    int myj = ((int)rank << 5) + t;   // valid for t < 32
    if (t < 32) {
        bhr = b_hh[myj]; bhz = b_hh[256 + myj]; bhn = b_hh[512 + myj];
    }
    if (t < 256) h_sm[0][t >> 6][t & 63] = 0.0f;
    __syncthreads();
    asm volatile("barrier.cluster.arrive.aligned;\n\t"
                 "barrier.cluster.wait.aligned;" ::: "memory");

    const float* xgb = xg + (size_t)b * S_LEN * G3 + grow;
    float* hb = all_h + (size_t)b * S_LEN * HID;
    uint32_t wsaddr = 0;
    if (t < 32)
        wsaddr = (uint32_t)__cvta_generic_to_shared(&h_sm[0][myj >> 6][myj & 63]);
    const uint32_t bufstride = 4u * 68u * 4u;   // bytes h_sm[0] -> h_sm[1]

#pragma unroll 1
    for (int s = 0; s < S_LEN; s++) {
        const int cur = s & 1;
        float xv = 0.0f;
        if (p == 0) xv = xgb[(size_t)s * G3];   // LDG, latency hidden by dot

        const float* hp = &h_sm[cur][p][0];
        float acc = 0.0f;
#pragma unroll
        for (int i = 0; i < 16; i++) {
            float4 hv = *(const float4*)(hp + (i << 2));
            acc = fmaf(w[i].x, hv.x, acc);
            acc = fmaf(w[i].y, hv.y, acc);
            acc = fmaf(w[i].z, hv.z, acc);
            acc = fmaf(w[i].w, hv.w, acc);
        }
        acc += __shfl_xor_sync(0xffffffffu, acc, 1);
        acc += __shfl_xor_sync(0xffffffffu, acc, 2);
        if (p == 0) { dots_sm[d] = acc; xg_sm[d] = xv; }
        __syncthreads();

        if (t < 32) {
            const float hr = dots_sm[t]      + bhr;
            const float hz = dots_sm[32 + t] + bhz;
            const float hn = dots_sm[64 + t] + bhn;
            const float r = sigmoidf_(xg_sm[t]      + hr);
            const float z = sigmoidf_(xg_sm[32 + t] + hz);
            const float n = tanhf(xg_sm[64 + t] + r * hn);
            const float hold = h_sm[cur][myj >> 6][myj & 63];
            const float hnew = (1.0f - z) * n + z * hold;
            hb[(size_t)s * HID + myj] = hnew;
            if (s == S_LEN - 1) hid_out[b * HID + myj] = hnew;
            const uint32_t dst = wsaddr + (uint32_t)(cur ^ 1) * bufstride;
#pragma unroll
            for (unsigned r8 = 0; r8 < 8; r8++) {
                uint32_t ra;
                asm volatile("mapa.shared::cluster.u32 %0, %1, %2;"
                             : "=r"(ra) : "r"(dst), "r"(r8));
                asm volatile("st.shared::cluster.f32 [%0], %1;"
                             :: "r"(ra), "f"(hnew));
            }
        }
        asm volatile("barrier.cluster.arrive.aligned;\n\t"
                     "barrier.cluster.wait.aligned;" ::: "memory");
    }
}

// ---------------------------------------------------------------------------
// Causal flash attention (fp32). Q = all_h, K = keys, V = all_h.
// One block per (b, 64-row q-tile). 256 threads. Online softmax.
// ---------------------------------------------------------------------------
#define ATTN_SMEM_FLOATS (256*64 + 256*64 + 64*260 + 64*65 + 192)
#define ATTN_SMEM_BYTES  (ATTN_SMEM_FLOATS * 4)

__global__ void __launch_bounds__(256, 1)
attn_kernel(const float* __restrict__ h, const float* __restrict__ keys,
            float* __restrict__ ctx)
{
    extern __shared__ float sm[];
    float* Qs = sm;                 // [256][64]  (k-major, transposed)
    float* Ks = Qs + 256 * 64;      // [256][64]
    float* Vs = Ks + 256 * 64;      // [64][260]  (row-major, padded)
    float* Ss = Vs + 64 * 260;      // [64][65]
    float* rm = Ss + 64 * 65;       // row max   [64]
    float* rl = rm + 64;            // row sum   [64]
    float* ra = rl + 64;            // row alpha [64]

    const int qt  = 31 - (int)blockIdx.x;   // long blocks first
    const int b   = blockIdx.y;
    const int tid = threadIdx.x;
    const int tx  = tid & 15;
    const int ty  = tid >> 4;
    const float* Hb = h    + (size_t)b * S_LEN * HID;
    const float* Kb = keys + (size_t)b * S_LEN * HID;

    // load Q tile transposed
#pragma unroll
    for (int it = 0; it < 16; it++) {
        const int e = it * 256 + tid;
        const int r = e >> 6, c4 = (e & 63) << 2;
        float4 v = *(const float4*)(Hb + (size_t)(qt * 64 + r) * HID + c4);
        Qs[(c4 + 0) * 64 + r] = v.x;
        Qs[(c4 + 1) * 64 + r] = v.y;
        Qs[(c4 + 2) * 64 + r] = v.z;
        Qs[(c4 + 3) * 64 + r] = v.w;
    }
    if (tid < 64) { rm[tid] = -1e30f; rl[tid] = 0.0f; }
    float acc[4][16];
#pragma unroll
    for (int i = 0; i < 4; i++)
#pragma unroll
        for (int j = 0; j < 16; j++) acc[i][j] = 0.0f;
    __syncthreads();

    for (int kt = 0; kt <= qt; kt++) {
        // load K tile (transposed) and V tile
#pragma unroll
        for (int it = 0; it < 16; it++) {
            const int e = it * 256 + tid;
            const int r = e >> 6, c4 = (e & 63) << 2;
            float4 kv = *(const float4*)(Kb + (size_t)(kt * 64 + r) * HID + c4);
            Ks[(c4 + 0) * 64 + r] = kv.x;
            Ks[(c4 + 1) * 64 + r] = kv.y;
            Ks[(c4 + 2) * 64 + r] = kv.z;
            Ks[(c4 + 3) * 64 + r] = kv.w;
            float4 vv = *(const float4*)(Hb + (size_t)(kt * 64 + r) * HID + c4);
            *(float4*)(Vs + r * 260 + c4) = vv;
        }
        __syncthreads();

        // S = Q @ K^T  (64x64, 4x4 per thread)
        float sv[4][4];
#pragma unroll
        for (int i = 0; i < 4; i++)
#pragma unroll
            for (int j = 0; j < 4; j++) sv[i][j] = 0.0f;
        for (int k = 0; k < 256; k++) {
            const float4 qa = *(const float4*)(Qs + k * 64 + ty * 4);
            const float4 kb = *(const float4*)(Ks + k * 64 + tx * 4);
            const float qv[4] = {qa.x, qa.y, qa.z, qa.w};
            const float kv[4] = {kb.x, kb.y, kb.z, kb.w};
#pragma unroll
            for (int i = 0; i < 4; i++)
#pragma unroll
                for (int j = 0; j < 4; j++)
                    sv[i][j] = fmaf(qv[i], kv[j], sv[i][j]);
        }
#pragma unroll
        for (int i = 0; i < 4; i++) {
            const int gi = qt * 64 + ty * 4 + i;
#pragma unroll
            for (int j = 0; j < 4; j++) {
                const int gj = kt * 64 + tx * 4 + j;
                Ss[(ty * 4 + i) * 65 + tx * 4 + j] = (gj > gi) ? -1e30f : sv[i][j];
            }
        }
        __syncthreads();

        // online softmax per row
        if (tid < 64) {
            float* srow = Ss + tid * 65;
            const float mo = rm[tid];
            float mx = mo;
#pragma unroll 8
            for (int j = 0; j < 64; j++) mx = fmaxf(mx, srow[j]);
            const float al = __expf(mo - mx);
            float sum = 0.0f;
#pragma unroll 8
            for (int j = 0; j < 64; j++) {
                const float pv = __expf(srow[j] - mx);
                srow[j] = pv;
                sum += pv;
            }
            rm[tid] = mx;
            rl[tid] = rl[tid] * al + sum;
            ra[tid] = al;
        }
        __syncthreads();

        // rescale + O += P @ V   (4 rows x 16 cols per thread)
        float alr[4];
#pragma unroll
        for (int i = 0; i < 4; i++) alr[i] = ra[ty * 4 + i];
#pragma unroll
        for (int i = 0; i < 4; i++)
#pragma unroll
            for (int j = 0; j < 16; j++) acc[i][j] *= alr[i];

        for (int j = 0; j < 64; j++) {
            const float p0 = Ss[(ty * 4 + 0) * 65 + j];
            const float p1 = Ss[(ty * 4 + 1) * 65 + j];
            const float p2 = Ss[(ty * 4 + 2) * 65 + j];
            const float p3 = Ss[(ty * 4 + 3) * 65 + j];
            const float* vrow = Vs + j * 260 + tx * 16;
#pragma unroll
            for (int q = 0; q < 4; q++) {
                const float4 vv = *(const float4*)(vrow + q * 4);
                acc[0][q*4+0] = fmaf(p0, vv.x, acc[0][q*4+0]);
                acc[0][q*4+1] = fmaf(p0, vv.y, acc[0][q*4+1]);
                acc[0][q*4+2] = fmaf(p0, vv.z, acc[0][q*4+2]);
                acc[0][q*4+3] = fmaf(p0, vv.w, acc[0][q*4+3]);
                acc[1][q*4+0] = fmaf(p1, vv.x, acc[1][q*4+0]);
                acc[1][q*4+1] = fmaf(p1, vv.y, acc[1][q*4+1]);
                acc[1][q*4+2] = fmaf(p1, vv.z, acc[1][q*4+2]);
                acc[1][q*4+3] = fmaf(p1, vv.w, acc[1][q*4+3]);
                acc[2][q*4+0] = fmaf(p2, vv.x, acc[2][q*4+0]);
                acc[2][q*4+1] = fmaf(p2, vv.y, acc[2][q*4+1]);
                acc[2][q*4+2] = fmaf(p2, vv.z, acc[2][q*4+2]);
                acc[2][q*4+3] = fmaf(p2, vv.w, acc[2][q*4+3]);
                acc[3][q*4+0] = fmaf(p3, vv.x, acc[3][q*4+0]);
                acc[3][q*4+1] = fmaf(p3, vv.y, acc[3][q*4+1]);
                acc[3][q*4+2] = fmaf(p3, vv.z, acc[3][q*4+2]);
                acc[3][q*4+3] = fmaf(p3, vv.w, acc[3][q*4+3]);
            }
        }
        __syncthreads();
    }

    float inv[4];
#pragma unroll
    for (int i = 0; i < 4; i++) inv[i] = 1.0f / rl[ty * 4 + i];
#pragma unroll
    for (int i = 0; i < 4; i++) {
        float* dst = ctx + ((size_t)b * S_LEN + qt * 64 + ty * 4 + i) * HID + tx * 16;
#pragma unroll
        for (int q = 0; q < 4; q++) {
            float4 o;
            o.x = acc[i][q * 4 + 0] * inv[i];
            o.y = acc[i][q * 4 + 1] * inv[i];
            o.z = acc[i][q * 4 + 2] * inv[i];
            o.w = acc[i][q * 4 + 3] * inv[i];
            *(float4*)(dst + q * 4) = o;
        }
    }
}

// ---------------------------------------------------------------------------
// Launch
// ---------------------------------------------------------------------------
extern "C" void kernel_launch(void* const* d_in, const int* in_sizes, int n_in,
                              void* d_out, int out_size)
{
    const int*   x      = (const int*)  d_in[0];
    const float* emb    = (const float*)d_in[1];
    const float* w_ih   = (const float*)d_in[2];
    const float* w_hh   = (const float*)d_in[3];
    const float* b_ih   = (const float*)d_in[4];
    const float* b_hh   = (const float*)d_in[5];
    const float* attn_w = (const float*)d_in[6];
    const float* attn_b = (const float*)d_in[7];
    const float* comb_w = (const float*)d_in[8];
    const float* comb_b = (const float*)d_in[9];
    const float* fc_w   = (const float*)d_in[10];
    const float* fc_b   = (const float*)d_in[11];
    float* out = (float*)d_out;

    float *xg, *h, *keys, *ctx, *comb;
    cudaGetSymbolAddress((void**)&xg,   g_xg);
    cudaGetSymbolAddress((void**)&h,    g_h);
    cudaGetSymbolAddress((void**)&keys, g_keys);
    cudaGetSymbolAddress((void**)&ctx,  g_ctx);
    cudaGetSymbolAddress((void**)&comb, g_comb);

    cudaFuncSetAttribute(attn_kernel,
                         cudaFuncAttributeMaxDynamicSharedMemorySize,
                         ATTN_SMEM_BYTES);

    // 1) xg = gather(embedding, x) @ w_ih^T + b_ih     [BS, 768]
    gemm_kernel<<<dim3(6, 128), 256>>>(emb, nullptr, EMBD, x,
                                       w_ih, b_ih, xg, BS, G3, EMBD, 0);
    // 2) GRU scan -> all_h, final hidden
    gru_kernel<<<64, 384>>>(xg, w_hh, b_hh, h, out + (size_t)BS * VOC);
    // 3) keys = all_h @ attn_w^T + attn_b              [BS, 256]
    gemm_kernel<<<dim3(2, 128), 256>>>(h, nullptr, HID, nullptr,
                                       attn_w, attn_b, keys, BS, HID, HID, 0);
    // 4) causal attention -> context
    attn_kernel<<<dim3(32, B_SZ), 256, ATTN_SMEM_BYTES>>>(h, keys, ctx);
    // 5) combined = tanh([all_h, ctx] @ comb_w^T + comb_b)
    gemm_kernel<<<dim3(2, 128), 256>>>(h, ctx, HID, nullptr,
                                       comb_w, comb_b, comb, BS, HID, 2 * HID, 1);
    // 6) output = combined @ fc_w^T + fc_b -> d_out    [BS, 100]
    gemm_kernel<<<dim3(1, 128), 256>>>(comb, nullptr, HID, nullptr,
                                       fc_w, fc_b, out, BS, VOC, HID, 0);
}